// round 1
// baseline (speedup 1.0000x reference)
#include <cuda_runtime.h>
#include <cstdint>
#include <cfloat>
#include <math.h>

#define NTOK 8192
#define DIMM 512
#define DEPTH 6
#define HEADS 8
#define DH 64
#define WSZ 256
#define INNER 512
#define FF 1365
#define FF2 2730

// Scratch (device globals; allocation is banned)
__device__ float g_x[NTOK * DIMM];
__device__ float g_qkv[NTOK * 3 * INNER];
__device__ float g_attn[NTOK * INNER];
__device__ float g_h[(size_t)NTOK * FF2];
__device__ float g_g[(size_t)NTOK * FF];

// ---------------------------------------------------------------------------
// Generic guarded SGEMM: C = A(MxK) @ B(KxN) [+ bias[N]] [+ res(MxN)]
// 128x128 tile, BK=16, 256 threads, 8x8 per-thread microtile.
// ---------------------------------------------------------------------------
__global__ void __launch_bounds__(256) sgemm_kernel(
    const float* __restrict__ A, const float* __restrict__ B,
    const float* __restrict__ bias, const float* __restrict__ res,
    float* __restrict__ C, int M, int N, int K)
{
    __shared__ float As[16][132];
    __shared__ float Bs[16][132];

    int bx = blockIdx.x;     // N tile
    int by = blockIdx.y;     // M tile
    int tid = threadIdx.x;
    int tx = tid & 15;
    int ty = tid >> 4;
    int row0 = by * 128 + ty * 8;
    int col0 = bx * 128 + tx * 8;

    float acc[8][8];
#pragma unroll
    for (int i = 0; i < 8; i++)
#pragma unroll
        for (int j = 0; j < 8; j++) acc[i][j] = 0.f;

    for (int k0 = 0; k0 < K; k0 += 16) {
        // Load A tile (128 rows x 16 k), thread covers 8 consecutive k of one row
#pragma unroll
        for (int i = 0; i < 8; i++) {
            int idx = tid * 8 + i;
            int r = idx >> 4;
            int kk = idx & 15;
            int gr = by * 128 + r, gk = k0 + kk;
            As[kk][r] = (gr < M && gk < K) ? A[(size_t)gr * K + gk] : 0.f;
        }
        // Load B tile (16 k x 128 cols), thread covers 8 consecutive cols of one k
#pragma unroll
        for (int i = 0; i < 8; i++) {
            int idx = tid * 8 + i;
            int kk = idx >> 7;
            int c = idx & 127;
            int gk = k0 + kk, gc = bx * 128 + c;
            Bs[kk][c] = (gk < K && gc < N) ? B[(size_t)gk * N + gc] : 0.f;
        }
        __syncthreads();

#pragma unroll
        for (int kk = 0; kk < 16; kk++) {
            float a[8], b[8];
            *(float4*)&a[0] = *(float4*)&As[kk][ty * 8];
            *(float4*)&a[4] = *(float4*)&As[kk][ty * 8 + 4];
            *(float4*)&b[0] = *(float4*)&Bs[kk][tx * 8];
            *(float4*)&b[4] = *(float4*)&Bs[kk][tx * 8 + 4];
#pragma unroll
            for (int i = 0; i < 8; i++)
#pragma unroll
                for (int j = 0; j < 8; j++) acc[i][j] += a[i] * b[j];
        }
        __syncthreads();
    }

#pragma unroll
    for (int i = 0; i < 8; i++) {
        int r = row0 + i;
        if (r >= M) break;
#pragma unroll
        for (int j = 0; j < 8; j++) {
            int c = col0 + j;
            if (c < N) {
                float v = acc[i][j];
                if (bias) v += bias[c];
                if (res) v += res[(size_t)r * N + c];
                C[(size_t)r * N + c] = v;
            }
        }
    }
}

// ---------------------------------------------------------------------------
// QK l2-norm * learned scale + xpos rotary. One warp per (pos, head).
// Lane handles dims (lane, lane+32) which is exactly the rotate_half pair.
// ---------------------------------------------------------------------------
__global__ void qknorm_rope_kernel(const float* __restrict__ qscale,
                                   const float* __restrict__ kscale)
{
    int task = blockIdx.x * 8 + (threadIdx.x >> 5);
    int lane = threadIdx.x & 31;
    int pos = task >> 3;
    int h = task & 7;

    float* qp = g_qkv + (size_t)pos * (3 * INNER) + h * DH;
    float* kp = qp + INNER;

    float q0 = qp[lane], q1 = qp[lane + 32];
    float k0 = kp[lane], k1 = kp[lane + 32];

    // l2 norm over 64 dims (warp reduce)
    float sq = q0 * q0 + q1 * q1;
    float sk = k0 * k0 + k1 * k1;
#pragma unroll
    for (int o = 16; o > 0; o >>= 1) {
        sq += __shfl_xor_sync(0xFFFFFFFF, sq, o);
        sk += __shfl_xor_sync(0xFFFFFFFF, sk, o);
    }
    float invq = 1.f / fmaxf(sqrtf(sq), 1e-12f);
    float invk = 1.f / fmaxf(sqrtf(sk), 1e-12f);
    q0 *= invq * qscale[lane];
    q1 *= invq * qscale[lane + 32];
    k0 *= invk * kscale[lane];
    k1 *= invk * kscale[lane + 32];

    // xpos rotary
    float t = (float)pos;
    float inv_freq = powf(10000.f, -(float)lane / 32.f);
    float fr = t * inv_freq;
    float c = cosf(fr), s = sinf(fr);
    float sv = (2.f * (float)lane + 0.4f * 64.f) / (1.4f * 64.f);
    float pw = (t - (float)(NTOK / 2)) / (float)(WSZ / 2);
    float xs = powf(sv, pw);
    float ixs = 1.f / xs;

    qp[lane]      = (q0 * c - q1 * s) * xs;
    qp[lane + 32] = (q1 * c + q0 * s) * xs;
    kp[lane]      = (k0 * c - k1 * s) * ixs;
    kp[lane + 32] = (k1 * c + k0 * s) * ixs;
}

// ---------------------------------------------------------------------------
// Local windowed attention. Block = (window w, head h), 256 threads,
// thread = one query row. Online softmax over 2 chunks of 256 keys.
// chunk0 (prev window): allowed j >= ti  -> iterate j descending (warp-uniform)
// chunk1 (own window):  allowed j <= ti  -> iterate j ascending  (warp-uniform)
// ---------------------------------------------------------------------------
__global__ void __launch_bounds__(256) local_attn_kernel()
{
    extern __shared__ float sm[];
    float* Ks = sm;                 // [256][64]
    float* Vs = sm + 256 * 64;      // [256][64]

    int w = blockIdx.x;
    int h = blockIdx.y;
    int ti = threadIdx.x;
    int qpos = w * WSZ + ti;

    const float* qp = g_qkv + (size_t)qpos * (3 * INNER) + h * DH;
    float4 q[16];
#pragma unroll
    for (int i = 0; i < 16; i++) q[i] = *(const float4*)(qp + 4 * i);

    float acc[64];
#pragma unroll
    for (int d = 0; d < 64; d++) acc[d] = 0.f;
    float m = -FLT_MAX, l = 0.f;

    int cstart = (w == 0) ? 1 : 0;
    for (int c = cstart; c < 2; c++) {
        __syncthreads();
        int kbase = (w - 1 + c) * WSZ;
        // cooperative K/V chunk load (16 float4 per thread per matrix)
#pragma unroll
        for (int i = 0; i < 16; i++) {
            int idx = ti * 16 + i;
            int row = idx >> 4;
            int d4 = (idx & 15) * 4;
            const float* kp = g_qkv + (size_t)(kbase + row) * (3 * INNER) + INNER + h * DH + d4;
            *(float4*)&Ks[row * 64 + d4] = *(const float4*)kp;
            *(float4*)&Vs[row * 64 + d4] = *(const float4*)(kp + INNER);
        }
        __syncthreads();

        if (c == 0) {
            for (int j = 255; j >= ti; j--) {
                const float4* krow = (const float4*)&Ks[j * 64];
                float s = 0.f;
#pragma unroll
                for (int i = 0; i < 16; i++) {
                    float4 kk = krow[i];
                    s += q[i].x * kk.x + q[i].y * kk.y + q[i].z * kk.z + q[i].w * kk.w;
                }
                s *= 8.0f;
                if (s > m) {
                    float sc = expf(m - s);
                    l *= sc;
#pragma unroll
                    for (int d = 0; d < 64; d++) acc[d] *= sc;
                    m = s;
                }
                float p = expf(s - m);
                l += p;
                const float* vrow = &Vs[j * 64];
#pragma unroll
                for (int d = 0; d < 64; d++) acc[d] += p * vrow[d];
            }
        } else {
            for (int j = 0; j <= ti; j++) {
                const float4* krow = (const float4*)&Ks[j * 64];
                float s = 0.f;
#pragma unroll
                for (int i = 0; i < 16; i++) {
                    float4 kk = krow[i];
                    s += q[i].x * kk.x + q[i].y * kk.y + q[i].z * kk.z + q[i].w * kk.w;
                }
                s *= 8.0f;
                if (s > m) {
                    float sc = expf(m - s);
                    l *= sc;
#pragma unroll
                    for (int d = 0; d < 64; d++) acc[d] *= sc;
                    m = s;
                }
                float p = expf(s - m);
                l += p;
                const float* vrow = &Vs[j * 64];
#pragma unroll
                for (int d = 0; d < 64; d++) acc[d] += p * vrow[d];
            }
        }
    }

    float invl = 1.f / l;
    float* op = g_attn + (size_t)qpos * INNER + h * DH;
#pragma unroll
    for (int d = 0; d < 64; d++) op[d] = acc[d] * invl;
}

// ---------------------------------------------------------------------------
// GLU with exact GELU: out = a * gelu(g), h = [a | g]
// ---------------------------------------------------------------------------
__global__ void glu_kernel()
{
    int idx = blockIdx.x * blockDim.x + threadIdx.x;
    if (idx >= NTOK * FF) return;
    int r = idx / FF;
    int jc = idx - r * FF;
    float a = g_h[(size_t)r * FF2 + jc];
    float g = g_h[(size_t)r * FF2 + FF + jc];
    float ge = 0.5f * g * (1.f + erff(g * 0.70710678118654752f));
    g_g[idx] = a * ge;
}

__global__ void copy_in_kernel(const float* __restrict__ src)
{
    int idx = blockIdx.x * blockDim.x + threadIdx.x;
    if (idx < NTOK * DIMM) g_x[idx] = src[idx];
}

// ---------------------------------------------------------------------------
extern "C" void kernel_launch(void* const* d_in, const int* in_sizes, int n_in,
                              void* d_out, int out_size)
{
    const float* x      = (const float*)d_in[0];
    const float* Wqkv   = (const float*)d_in[1];
    const float* Wo     = (const float*)d_in[2];
    const float* qscale = (const float*)d_in[3];
    const float* kscale = (const float*)d_in[4];
    const float* W1     = (const float*)d_in[5];
    const float* b1     = (const float*)d_in[6];
    const float* W2     = (const float*)d_in[7];
    const float* b2     = (const float*)d_in[8];

    float *px, *pqkv, *pattn, *ph, *pg;
    cudaGetSymbolAddress((void**)&px, g_x);
    cudaGetSymbolAddress((void**)&pqkv, g_qkv);
    cudaGetSymbolAddress((void**)&pattn, g_attn);
    cudaGetSymbolAddress((void**)&ph, g_h);
    cudaGetSymbolAddress((void**)&pg, g_g);

    cudaFuncSetAttribute(local_attn_kernel,
                         cudaFuncAttributeMaxDynamicSharedMemorySize, 2 * 256 * 64 * 4);

    copy_in_kernel<<<(NTOK * DIMM + 255) / 256, 256>>>(x);

    for (int lyr = 0; lyr < DEPTH; lyr++) {
        // 1) QKV projection
        sgemm_kernel<<<dim3((3 * INNER) / 128, NTOK / 128), 256>>>(
            px, Wqkv + (size_t)lyr * DIMM * 3 * INNER, nullptr, nullptr,
            pqkv, NTOK, 3 * INNER, DIMM);

        // 2) qk norm + xpos rotary (in place on g_qkv)
        qknorm_rope_kernel<<<NTOK, 256>>>(qscale + lyr * DH, kscale + lyr * DH);

        // 3) local attention
        local_attn_kernel<<<dim3(NTOK / WSZ, HEADS), 256, 2 * 256 * 64 * 4>>>();

        // 4) output projection + residual  (x = attn @ Wo + x)
        sgemm_kernel<<<dim3(DIMM / 128, NTOK / 128), 256>>>(
            pattn, Wo + (size_t)lyr * INNER * DIMM, nullptr, px,
            px, NTOK, DIMM, INNER);

        // 5) FF up projection + b1
        sgemm_kernel<<<dim3((FF2 + 127) / 128, NTOK / 128), 256>>>(
            px, W1 + (size_t)lyr * DIMM * FF2, b1 + (size_t)lyr * FF2, nullptr,
            ph, NTOK, FF2, DIMM);

        // 6) gated GELU
        glu_kernel<<<(NTOK * FF + 255) / 256, 256>>>();

        // 7) FF down projection + b2 + residual
        float* outp = (lyr == DEPTH - 1) ? (float*)d_out : px;
        sgemm_kernel<<<dim3(DIMM / 128, NTOK / 128), 256>>>(
            pg, W2 + (size_t)lyr * FF * DIMM, b2 + (size_t)lyr * DIMM, px,
            outp, NTOK, DIMM, FF);
    }
}

// round 3
// speedup vs baseline: 1.8144x; 1.8144x over previous
#include <cuda_runtime.h>
#include <cuda_bf16.h>
#include <cstdint>
#include <cfloat>
#include <math.h>

#define NTOK 8192
#define DIMM 512
#define DEPTH 6
#define HEADS 8
#define DH 64
#define WSZ 256
#define INNER 512
#define FF 1365
#define FF2 2730

// Scratch (device globals; allocation is banned)
__device__ float g_x[NTOK * DIMM];
__device__ float g_qkv[NTOK * 3 * INNER];
__device__ float g_attn[NTOK * INNER];
__device__ float g_h[(size_t)NTOK * FF2];
__device__ float g_g[(size_t)NTOK * FF];

__device__ __forceinline__ uint32_t smem_to_u32(const void* p) {
    uint32_t a;
    asm("{ .reg .u64 t; cvta.to.shared.u64 t, %1; cvt.u32.u64 %0, t; }" : "=r"(a) : "l"(p));
    return a;
}

// ---------------------------------------------------------------------------
// Swizzled smem layout for bf16 tiles of [128 rows][32 k]:
// two logical rows share one 128B physical row; 16B chunk index is XORed
// with (physical_row & 7).  Conflict-free for STS.128 writes and ldmatrix.
// ---------------------------------------------------------------------------
__device__ __forceinline__ uint32_t swz(int r, int chunk) {
    int pr = r >> 1;
    int cc = ((r & 1) << 2) | chunk;   // 0..7
    cc ^= (pr & 7);
    return (uint32_t)(pr * 128 + cc * 16);
}

__device__ __forceinline__ void split8(const float* v, uint4& hi, uint4& lo) {
    uint32_t hw[4], lw[4];
#pragma unroll
    for (int i = 0; i < 4; i++) {
        __nv_bfloat162 h = __floats2bfloat162_rn(v[2 * i], v[2 * i + 1]);
        float2 hf = __bfloat1622float2(h);
        __nv_bfloat162 l = __floats2bfloat162_rn(v[2 * i] - hf.x, v[2 * i + 1] - hf.y);
        hw[i] = *reinterpret_cast<uint32_t*>(&h);
        lw[i] = *reinterpret_cast<uint32_t*>(&l);
    }
    hi = make_uint4(hw[0], hw[1], hw[2], hw[3]);
    lo = make_uint4(lw[0], lw[1], lw[2], lw[3]);
}

__device__ __forceinline__ void ldx4(uint32_t& d0, uint32_t& d1, uint32_t& d2, uint32_t& d3,
                                     uint32_t addr) {
    asm volatile("ldmatrix.sync.aligned.m8n8.x4.shared.b16 {%0,%1,%2,%3}, [%4];"
                 : "=r"(d0), "=r"(d1), "=r"(d2), "=r"(d3) : "r"(addr));
}

__device__ __forceinline__ void mma16816(float* c, uint32_t a0, uint32_t a1, uint32_t a2,
                                         uint32_t a3, uint32_t b0, uint32_t b1) {
    asm volatile(
        "mma.sync.aligned.m16n8k16.row.col.f32.bf16.bf16.f32 "
        "{%0,%1,%2,%3}, {%4,%5,%6,%7}, {%8,%9}, {%0,%1,%2,%3};"
        : "+f"(c[0]), "+f"(c[1]), "+f"(c[2]), "+f"(c[3])
        : "r"(a0), "r"(a1), "r"(a2), "r"(a3), "r"(b0), "r"(b1));
}

// ===========================================================================
// Tensor-core GEMM:  C(MxN) = A(MxK) @ B(KxN)  [+bias[N]] [+res(MxN)]
// fp32 in/out, bf16x3 split, 128x128x32 tile, 256 threads.
// smem: Ah@0, Al@8192, Bh@16384, Bl@24576 (each 128x32 bf16 = 8192B)
// ===========================================================================
#define GEMM_SMEM (32768 + 1024)

__global__ void __launch_bounds__(256) tc_gemm_kernel(
    const float* __restrict__ A, const float* __restrict__ B,
    const float* __restrict__ bias, const float* __restrict__ res,
    float* __restrict__ C, int M, int N, int K)
{
    extern __shared__ char smraw[];
    char* sm = (char*)(((uintptr_t)smraw + 1023) & ~(uintptr_t)1023);
    uint32_t sb = smem_to_u32(sm);

    int tid = threadIdx.x;
    int wid = tid >> 5;
    int lane = tid & 31;
    int mw = wid >> 1;          // 0..3 -> rows mw*32
    int nw = wid & 1;           // 0..1 -> cols nw*64
    int m0 = blockIdx.y * 128;
    int n0 = blockIdx.x * 128;

    // ldmatrix lane base addresses (chunk base 0; kk=1 -> ^32, lo -> +8192)
    uint32_t aAddr[2], bAddr[4];
    {
        int t = lane >> 3, l7 = lane & 7;
#pragma unroll
        for (int mi = 0; mi < 2; mi++) {
            int r = mw * 32 + mi * 16 + ((t & 1) << 3) + l7;
            aAddr[mi] = sb + swz(r, t >> 1);
        }
#pragma unroll
        for (int j = 0; j < 4; j++) {
            int r = nw * 64 + j * 16 + ((t >> 1) << 3) + l7;
            bAddr[j] = sb + 16384 + swz(r, t & 1);
        }
    }

    float acc[2][8][4];
#pragma unroll
    for (int mi = 0; mi < 2; mi++)
#pragma unroll
        for (int j = 0; j < 8; j++)
#pragma unroll
            for (int q = 0; q < 4; q++) acc[mi][j][q] = 0.f;

    const int niter = (K + 31) / 32;

    // per-thread load slots
    int arow = tid >> 1;
    int akoff = (tid & 1) * 16;
    int bn = tid & 127;
    int bkoff = (tid >> 7) * 16;
    bool bnok = (n0 + bn) < N;

    uint4 pAh[2], pAl[2], pBh[2], pBl[2];

    // ---- load tile 0 ----
    {
        int k0 = 0;
        float v[16];
        const float* ap = A + (size_t)(m0 + arow) * K + akoff;
        if ((K & 3) == 0 && 32 <= K) {
#pragma unroll
            for (int q = 0; q < 4; q++) *(float4*)&v[q * 4] = *(const float4*)(ap + q * 4);
        } else {
#pragma unroll
            for (int j = 0; j < 16; j++) v[j] = (akoff + j < K) ? ap[j] : 0.f;
        }
        split8(v, pAh[0], pAl[0]); split8(v + 8, pAh[1], pAl[1]);
        const float* bp = B + (size_t)(k0 + bkoff) * N + n0 + bn;
#pragma unroll
        for (int j = 0; j < 16; j++)
            v[j] = (bnok && (bkoff + j) < K) ? bp[(size_t)j * N] : 0.f;
        split8(v, pBh[0], pBl[0]); split8(v + 8, pBh[1], pBl[1]);
    }
    {
        int c = (tid & 1) * 2;
        *(uint4*)(sm + swz(arow, c)) = pAh[0];
        *(uint4*)(sm + swz(arow, c + 1)) = pAh[1];
        *(uint4*)(sm + 8192 + swz(arow, c)) = pAl[0];
        *(uint4*)(sm + 8192 + swz(arow, c + 1)) = pAl[1];
        int bc = (tid >> 7) * 2;
        *(uint4*)(sm + 16384 + swz(bn, bc)) = pBh[0];
        *(uint4*)(sm + 16384 + swz(bn, bc + 1)) = pBh[1];
        *(uint4*)(sm + 24576 + swz(bn, bc)) = pBl[0];
        *(uint4*)(sm + 24576 + swz(bn, bc + 1)) = pBl[1];
    }
    __syncthreads();

    for (int it = 0; it < niter; ++it) {
        bool more = (it + 1) < niter;
        // ---- prefetch next tile into regs ----
        if (more) {
            int k0 = (it + 1) * 32;
            float v[16];
            const float* ap = A + (size_t)(m0 + arow) * K + k0 + akoff;
            if ((K & 3) == 0 && k0 + 32 <= K) {
#pragma unroll
                for (int q = 0; q < 4; q++) *(float4*)&v[q * 4] = *(const float4*)(ap + q * 4);
            } else {
#pragma unroll
                for (int j = 0; j < 16; j++) v[j] = (k0 + akoff + j < K) ? ap[j] : 0.f;
            }
            split8(v, pAh[0], pAl[0]); split8(v + 8, pAh[1], pAl[1]);
            const float* bp = B + (size_t)(k0 + bkoff) * N + n0 + bn;
#pragma unroll
            for (int j = 0; j < 16; j++)
                v[j] = (bnok && (k0 + bkoff + j) < K) ? bp[(size_t)j * N] : 0.f;
            split8(v, pBh[0], pBl[0]); split8(v + 8, pBl[1], pBl[1]);
            // NOTE: fix aliasing of pBh[1]: recompute correctly below
            split8(v, pBh[0], pBl[0]); split8(v + 8, pBh[1], pBl[1]);
        }

        // ---- compute current tile ----
#pragma unroll
        for (int kk = 0; kk < 2; kk++) {
            uint32_t x = kk * 32;
            uint32_t ah[2][4], bh[4][4];
            ldx4(ah[0][0], ah[0][1], ah[0][2], ah[0][3], aAddr[0] ^ x);
            ldx4(ah[1][0], ah[1][1], ah[1][2], ah[1][3], aAddr[1] ^ x);
#pragma unroll
            for (int j = 0; j < 4; j++)
                ldx4(bh[j][0], bh[j][1], bh[j][2], bh[j][3], bAddr[j] ^ x);
            // Ah * Bh
#pragma unroll
            for (int mi = 0; mi < 2; mi++)
#pragma unroll
                for (int j = 0; j < 4; j++) {
                    mma16816(acc[mi][2 * j],     ah[mi][0], ah[mi][1], ah[mi][2], ah[mi][3], bh[j][0], bh[j][1]);
                    mma16816(acc[mi][2 * j + 1], ah[mi][0], ah[mi][1], ah[mi][2], ah[mi][3], bh[j][2], bh[j][3]);
                }
            // Ah * Bl
#pragma unroll
            for (int j = 0; j < 4; j++) {
                uint32_t bl[4];
                ldx4(bl[0], bl[1], bl[2], bl[3], (bAddr[j] ^ x) + 8192);
#pragma unroll
                for (int mi = 0; mi < 2; mi++) {
                    mma16816(acc[mi][2 * j],     ah[mi][0], ah[mi][1], ah[mi][2], ah[mi][3], bl[0], bl[1]);
                    mma16816(acc[mi][2 * j + 1], ah[mi][0], ah[mi][1], ah[mi][2], ah[mi][3], bl[2], bl[3]);
                }
            }
            // Al * Bh
            ldx4(ah[0][0], ah[0][1], ah[0][2], ah[0][3], (aAddr[0] ^ x) + 8192);
            ldx4(ah[1][0], ah[1][1], ah[1][2], ah[1][3], (aAddr[1] ^ x) + 8192);
#pragma unroll
            for (int mi = 0; mi < 2; mi++)
#pragma unroll
                for (int j = 0; j < 4; j++) {
                    mma16816(acc[mi][2 * j],     ah[mi][0], ah[mi][1], ah[mi][2], ah[mi][3], bh[j][0], bh[j][1]);
                    mma16816(acc[mi][2 * j + 1], ah[mi][0], ah[mi][1], ah[mi][2], ah[mi][3], bh[j][2], bh[j][3]);
                }
        }
        __syncthreads();

        // ---- store prefetched regs to smem ----
        if (more) {
            int c = (tid & 1) * 2;
            *(uint4*)(sm + swz(arow, c)) = pAh[0];
            *(uint4*)(sm + swz(arow, c + 1)) = pAh[1];
            *(uint4*)(sm + 8192 + swz(arow, c)) = pAl[0];
            *(uint4*)(sm + 8192 + swz(arow, c + 1)) = pAl[1];
            int bc = (tid >> 7) * 2;
            *(uint4*)(sm + 16384 + swz(bn, bc)) = pBh[0];
            *(uint4*)(sm + 16384 + swz(bn, bc + 1)) = pBh[1];
            *(uint4*)(sm + 24576 + swz(bn, bc)) = pBl[0];
            *(uint4*)(sm + 24576 + swz(bn, bc + 1)) = pBl[1];
            __syncthreads();
        }
    }

    // ---- epilogue: direct STG.64 with fused bias/residual ----
#pragma unroll
    for (int mi = 0; mi < 2; mi++) {
        int rbase = m0 + mw * 32 + mi * 16 + (lane >> 2);
#pragma unroll
        for (int j = 0; j < 8; j++) {
            int col = n0 + nw * 64 + j * 8 + (lane & 3) * 2;
            if (col < N) {
                float bx = 0.f, by = 0.f;
                if (bias) { bx = bias[col]; by = bias[col + 1]; }
#pragma unroll
                for (int half = 0; half < 2; half++) {
                    int r = rbase + half * 8;
                    size_t o = (size_t)r * N + col;
                    float v0 = acc[mi][j][half * 2] + bx;
                    float v1 = acc[mi][j][half * 2 + 1] + by;
                    if (res) { v0 += res[o]; v1 += res[o + 1]; }
                    float2 out = make_float2(v0, v1);
                    *(float2*)(C + o) = out;
                }
            }
        }
    }
}

// ---------------------------------------------------------------------------
// QK l2-norm * learned scale + xpos rotary. One warp per (pos, head).
// ---------------------------------------------------------------------------
__global__ void qknorm_rope_kernel(const float* __restrict__ qscale,
                                   const float* __restrict__ kscale)
{
    int task = blockIdx.x * 8 + (threadIdx.x >> 5);
    int lane = threadIdx.x & 31;
    int pos = task >> 3;
    int h = task & 7;

    float* qp = g_qkv + (size_t)pos * (3 * INNER) + h * DH;
    float* kp = qp + INNER;

    float q0 = qp[lane], q1 = qp[lane + 32];
    float k0 = kp[lane], k1 = kp[lane + 32];

    float sq = q0 * q0 + q1 * q1;
    float sk = k0 * k0 + k1 * k1;
#pragma unroll
    for (int o = 16; o > 0; o >>= 1) {
        sq += __shfl_xor_sync(0xFFFFFFFF, sq, o);
        sk += __shfl_xor_sync(0xFFFFFFFF, sk, o);
    }
    float invq = 1.f / fmaxf(sqrtf(sq), 1e-12f);
    float invk = 1.f / fmaxf(sqrtf(sk), 1e-12f);
    q0 *= invq * qscale[lane];
    q1 *= invq * qscale[lane + 32];
    k0 *= invk * kscale[lane];
    k1 *= invk * kscale[lane + 32];

    float t = (float)pos;
    float inv_freq = powf(10000.f, -(float)lane / 32.f);
    float fr = t * inv_freq;
    float c = cosf(fr), s = sinf(fr);
    float sv = (2.f * (float)lane + 0.4f * 64.f) / (1.4f * 64.f);
    float pw = (t - (float)(NTOK / 2)) / (float)(WSZ / 2);
    float xs = powf(sv, pw);
    float ixs = 1.f / xs;

    qp[lane]      = (q0 * c - q1 * s) * xs;
    qp[lane + 32] = (q1 * c + q0 * s) * xs;
    kp[lane]      = (k0 * c - k1 * s) * ixs;
    kp[lane + 32] = (k1 * c + k0 * s) * ixs;
}

// ---------------------------------------------------------------------------
// Local windowed attention (unchanged; 332us/layer).
// ---------------------------------------------------------------------------
__global__ void __launch_bounds__(256) local_attn_kernel()
{
    extern __shared__ float smf[];
    float* Ks = smf;
    float* Vs = smf + 256 * 64;

    int w = blockIdx.x;
    int h = blockIdx.y;
    int ti = threadIdx.x;
    int qpos = w * WSZ + ti;

    const float* qp = g_qkv + (size_t)qpos * (3 * INNER) + h * DH;
    float4 q[16];
#pragma unroll
    for (int i = 0; i < 16; i++) q[i] = *(const float4*)(qp + 4 * i);

    float acc[64];
#pragma unroll
    for (int d = 0; d < 64; d++) acc[d] = 0.f;
    float m = -FLT_MAX, l = 0.f;

    int cstart = (w == 0) ? 1 : 0;
    for (int c = cstart; c < 2; c++) {
        __syncthreads();
        int kbase = (w - 1 + c) * WSZ;
#pragma unroll
        for (int i = 0; i < 16; i++) {
            int idx = ti * 16 + i;
            int row = idx >> 4;
            int d4 = (idx & 15) * 4;
            const float* kp = g_qkv + (size_t)(kbase + row) * (3 * INNER) + INNER + h * DH + d4;
            *(float4*)&Ks[row * 64 + d4] = *(const float4*)kp;
            *(float4*)&Vs[row * 64 + d4] = *(const float4*)(kp + INNER);
        }
        __syncthreads();

        if (c == 0) {
            for (int j = 255; j >= ti; j--) {
                const float4* krow = (const float4*)&Ks[j * 64];
                float s = 0.f;
#pragma unroll
                for (int i = 0; i < 16; i++) {
                    float4 kk = krow[i];
                    s += q[i].x * kk.x + q[i].y * kk.y + q[i].z * kk.z + q[i].w * kk.w;
                }
                s *= 8.0f;
                if (s > m) {
                    float sc = expf(m - s);
                    l *= sc;
#pragma unroll
                    for (int d = 0; d < 64; d++) acc[d] *= sc;
                    m = s;
                }
                float p = expf(s - m);
                l += p;
                const float* vrow = &Vs[j * 64];
#pragma unroll
                for (int d = 0; d < 64; d++) acc[d] += p * vrow[d];
            }
        } else {
            for (int j = 0; j <= ti; j++) {
                const float4* krow = (const float4*)&Ks[j * 64];
                float s = 0.f;
#pragma unroll
                for (int i = 0; i < 16; i++) {
                    float4 kk = krow[i];
                    s += q[i].x * kk.x + q[i].y * kk.y + q[i].z * kk.z + q[i].w * kk.w;
                }
                s *= 8.0f;
                if (s > m) {
                    float sc = expf(m - s);
                    l *= sc;
#pragma unroll
                    for (int d = 0; d < 64; d++) acc[d] *= sc;
                    m = s;
                }
                float p = expf(s - m);
                l += p;
                const float* vrow = &Vs[j * 64];
#pragma unroll
                for (int d = 0; d < 64; d++) acc[d] += p * vrow[d];
            }
        }
    }

    float invl = 1.f / l;
    float* op = g_attn + (size_t)qpos * INNER + h * DH;
#pragma unroll
    for (int d = 0; d < 64; d++) op[d] = acc[d] * invl;
}

// ---------------------------------------------------------------------------
__global__ void glu_kernel()
{
    int idx = blockIdx.x * blockDim.x + threadIdx.x;
    if (idx >= NTOK * FF) return;
    int r = idx / FF;
    int jc = idx - r * FF;
    float a = g_h[(size_t)r * FF2 + jc];
    float g = g_h[(size_t)r * FF2 + FF + jc];
    float ge = 0.5f * g * (1.f + erff(g * 0.70710678118654752f));
    g_g[idx] = a * ge;
}

__global__ void copy_in_kernel(const float* __restrict__ src)
{
    int idx = blockIdx.x * blockDim.x + threadIdx.x;
    if (idx < NTOK * DIMM) g_x[idx] = src[idx];
}

// ---------------------------------------------------------------------------
extern "C" void kernel_launch(void* const* d_in, const int* in_sizes, int n_in,
                              void* d_out, int out_size)
{
    const float* x      = (const float*)d_in[0];
    const float* Wqkv   = (const float*)d_in[1];
    const float* Wo     = (const float*)d_in[2];
    const float* qscale = (const float*)d_in[3];
    const float* kscale = (const float*)d_in[4];
    const float* W1     = (const float*)d_in[5];
    const float* b1     = (const float*)d_in[6];
    const float* W2     = (const float*)d_in[7];
    const float* b2     = (const float*)d_in[8];

    float *px, *pqkv, *pattn, *ph, *pg;
    cudaGetSymbolAddress((void**)&px, g_x);
    cudaGetSymbolAddress((void**)&pqkv, g_qkv);
    cudaGetSymbolAddress((void**)&pattn, g_attn);
    cudaGetSymbolAddress((void**)&ph, g_h);
    cudaGetSymbolAddress((void**)&pg, g_g);

    cudaFuncSetAttribute(local_attn_kernel,
                         cudaFuncAttributeMaxDynamicSharedMemorySize, 2 * 256 * 64 * 4);

    copy_in_kernel<<<(NTOK * DIMM + 255) / 256, 256>>>(x);

    for (int lyr = 0; lyr < DEPTH; lyr++) {
        // 1) QKV projection
        tc_gemm_kernel<<<dim3((3 * INNER + 127) / 128, NTOK / 128), 256, GEMM_SMEM>>>(
            px, Wqkv + (size_t)lyr * DIMM * 3 * INNER, nullptr, nullptr,
            pqkv, NTOK, 3 * INNER, DIMM);

        // 2) qk norm + xpos rotary
        qknorm_rope_kernel<<<NTOK, 256>>>(qscale + lyr * DH, kscale + lyr * DH);

        // 3) local attention
        local_attn_kernel<<<dim3(NTOK / WSZ, HEADS), 256, 2 * 256 * 64 * 4>>>();

        // 4) output projection + residual
        tc_gemm_kernel<<<dim3(DIMM / 128, NTOK / 128), 256, GEMM_SMEM>>>(
            pattn, Wo + (size_t)lyr * INNER * DIMM, nullptr, px,
            px, NTOK, DIMM, INNER);

        // 5) FF up projection + b1
        tc_gemm_kernel<<<dim3((FF2 + 127) / 128, NTOK / 128), 256, GEMM_SMEM>>>(
            px, W1 + (size_t)lyr * DIMM * FF2, b1 + (size_t)lyr * FF2, nullptr,
            ph, NTOK, FF2, DIMM);

        // 6) gated GELU
        glu_kernel<<<(NTOK * FF + 255) / 256, 256>>>();

        // 7) FF down projection + b2 + residual
        float* outp = (lyr == DEPTH - 1) ? (float*)d_out : px;
        tc_gemm_kernel<<<dim3(DIMM / 128, NTOK / 128), 256, GEMM_SMEM>>>(
            pg, W2 + (size_t)lyr * FF * DIMM, b2 + (size_t)lyr * DIMM, px,
            outp, NTOK, DIMM, FF);
    }
}